// round 2
// baseline (speedup 1.0000x reference)
#include <cuda_runtime.h>
#include <math.h>

#define NN 100000
#define EE 1600000
#define SCAN_BS 1024
#define SCAN_NB ((NN + SCAN_BS - 1) / SCAN_BS)   // 98

// ---------------- scratch (static device globals; no allocation) ------------
__device__ float g_xl[NN * 50];
__device__ float g_xr[NN * 50];
__device__ float g_h[NN * 150];
__device__ int   g_rowptr[NN + 1];
__device__ int   g_cursor[NN];
__device__ int   g_csr[EE];
__device__ int   g_bsums[SCAN_BS];

// ---------------- CSR build -------------------------------------------------
__global__ void zero_cursor_kernel() {
    int i = blockIdx.x * blockDim.x + threadIdx.x;
    if (i < NN) g_cursor[i] = 0;
}

__global__ void hist_kernel(const int* __restrict__ dst) {
    for (int e = blockIdx.x * blockDim.x + threadIdx.x; e < EE;
         e += gridDim.x * blockDim.x) {
        atomicAdd(&g_cursor[dst[e]], 1);
    }
}

// block-level exclusive scan of g_cursor -> g_rowptr, block sums to g_bsums
__global__ void scan1_kernel() {
    __shared__ int sh[SCAN_BS];
    int tid = threadIdx.x;
    int i = blockIdx.x * SCAN_BS + tid;
    int v = (i < NN) ? g_cursor[i] : 0;
    sh[tid] = v;
    __syncthreads();
    for (int off = 1; off < SCAN_BS; off <<= 1) {
        int t = (tid >= off) ? sh[tid - off] : 0;
        __syncthreads();
        sh[tid] += t;
        __syncthreads();
    }
    if (i < NN) g_rowptr[i] = sh[tid] - v;            // exclusive within block
    if (tid == SCAN_BS - 1) g_bsums[blockIdx.x] = sh[tid];
}

// single-block exclusive scan of g_bsums in place
__global__ void scan2_kernel() {
    __shared__ int sh[SCAN_BS];
    int tid = threadIdx.x;
    int v = (tid < SCAN_NB) ? g_bsums[tid] : 0;
    sh[tid] = v;
    __syncthreads();
    for (int off = 1; off < SCAN_BS; off <<= 1) {
        int t = (tid >= off) ? sh[tid - off] : 0;
        __syncthreads();
        sh[tid] += t;
        __syncthreads();
    }
    if (tid < SCAN_NB) g_bsums[tid] = sh[tid] - v;    // exclusive
}

__global__ void scan3_kernel() {
    int i = blockIdx.x * SCAN_BS + threadIdx.x;
    if (i < NN) {
        int r = g_rowptr[i] + g_bsums[blockIdx.x];
        g_rowptr[i] = r;
        g_cursor[i] = r;                               // scatter cursor
    }
    if (blockIdx.x == 0 && threadIdx.x == 0) g_rowptr[NN] = EE;
}

__global__ void scatter_kernel(const int* __restrict__ src,
                               const int* __restrict__ dst) {
    for (int e = blockIdx.x * blockDim.x + threadIdx.x; e < EE;
         e += gridDim.x * blockDim.x) {
        int p = atomicAdd(&g_cursor[dst[e]], 1);
        g_csr[p] = src[e];
    }
}

// ---------------- xl = x@Wl+bl, xr = x@Wr+br --------------------------------
__global__ void lin_kernel(const float* __restrict__ x,
                           const float* __restrict__ Wl, const float* __restrict__ bl,
                           const float* __restrict__ Wr, const float* __restrict__ br) {
    int id = blockIdx.x * blockDim.x + threadIdx.x;
    if (id >= NN * 50) return;
    int node = id / 50;
    int c = id - node * 50;
    const float* xrow = x + node * 25;
    float al = bl[c], ar = br[c];
#pragma unroll
    for (int k = 0; k < 25; k++) {
        float xv = __ldg(&xrow[k]);
        al += xv * __ldg(&Wl[k * 50 + c]);
        ar += xv * __ldg(&Wr[k * 50 + c]);
    }
    g_xl[id] = al;
    g_xr[id] = ar;
}

// ---------------- GATv2 aggregate: one warp per node ------------------------
__global__ void aggregate_kernel(const float* __restrict__ att,
                                 const float* __restrict__ bo,
                                 int tag_off) {
    int warp = (blockIdx.x * blockDim.x + threadIdx.x) >> 5;
    int lane = threadIdx.x & 31;
    if (warp >= NN) return;
    const int i = warp;
    bool hi = (lane < 18);

    float xr0 = g_xr[i * 50 + lane];
    float xr1 = hi ? g_xr[i * 50 + 32 + lane] : 0.f;
    float xl0 = g_xl[i * 50 + lane];
    float xl1 = hi ? g_xl[i * 50 + 32 + lane] : 0.f;
    float a0 = __ldg(&att[lane]);
    float a1 = hi ? __ldg(&att[32 + lane]) : 0.f;

    // self loop
    float m0 = xl0 + xr0; m0 = (m0 > 0.f) ? m0 : 0.2f * m0;
    float m1 = xl1 + xr1; m1 = (m1 > 0.f) ? m1 : 0.2f * m1;
    float p = m0 * a0 + m1 * a1;
#pragma unroll
    for (int o = 16; o; o >>= 1) p += __shfl_xor_sync(0xFFFFFFFFu, p, o);
    float w = expf(p);
    float denom = w;
    float acc0 = w * xl0;
    float acc1 = w * xl1;

    int beg = g_rowptr[i];
    int end = g_rowptr[i + 1];
    for (int e = beg; e < end; ++e) {
        int j = g_csr[e];
        float y0 = g_xl[j * 50 + lane];
        float y1 = hi ? g_xl[j * 50 + 32 + lane] : 0.f;
        float q0 = y0 + xr0; q0 = (q0 > 0.f) ? q0 : 0.2f * q0;
        float q1 = y1 + xr1; q1 = (q1 > 0.f) ? q1 : 0.2f * q1;
        float s = q0 * a0 + q1 * a1;
#pragma unroll
        for (int o = 16; o; o >>= 1) s += __shfl_xor_sync(0xFFFFFFFFu, s, o);
        float we = expf(s);
        denom += we;
        acc0 += we * y0;
        acc1 += we * y1;
    }

    float inv = 1.f / denom;
    float o0 = acc0 * inv + __ldg(&bo[lane]);
    o0 = (o0 > 0.f) ? o0 : 0.1f * o0;
    g_h[i * 150 + tag_off + lane] = o0;
    if (hi) {
        float o1 = acc1 * inv + __ldg(&bo[32 + lane]);
        o1 = (o1 > 0.f) ? o1 : 0.1f * o1;
        g_h[i * 150 + tag_off + 32 + lane] = o1;
    }
}

// ---------------- MLP head: one warp per node -------------------------------
__global__ void mlp_kernel(const float* __restrict__ pW, const float* __restrict__ pb,
                           const float* __restrict__ W1, const float* __restrict__ b1,
                           const float* __restrict__ W2, const float* __restrict__ b2,
                           const float* __restrict__ W3, const float* __restrict__ b3,
                           float* __restrict__ out) {
    __shared__ float shA[8][152];
    __shared__ float shB[8][152];
    int wid = threadIdx.x >> 5;
    int lane = threadIdx.x & 31;
    int node = blockIdx.x * 8 + wid;
    if (node >= NN) return;
    float* A = shA[wid];
    float* B = shB[wid];

    for (int d = lane; d < 150; d += 32) A[d] = g_h[node * 150 + d];
    __syncwarp();

    // proj: 150 -> 150 (no activation)
    for (int c = lane; c < 150; c += 32) {
        float acc = __ldg(&pb[c]);
        for (int k = 0; k < 150; k++) acc += A[k] * __ldg(&pW[k * 150 + c]);
        B[c] = acc;
    }
    __syncwarp();

    // cls layer 1: 150 -> 75, leaky 0.1
    for (int c = lane; c < 75; c += 32) {
        float acc = __ldg(&b1[c]);
        for (int k = 0; k < 150; k++) acc += B[k] * __ldg(&W1[k * 75 + c]);
        A[c] = (acc > 0.f) ? acc : 0.1f * acc;
    }
    __syncwarp();

    // cls layer 2: 75 -> 30, leaky 0.1
    for (int c = lane; c < 30; c += 32) {
        float acc = __ldg(&b2[c]);
        for (int k = 0; k < 75; k++) acc += A[k] * __ldg(&W2[k * 30 + c]);
        B[c] = (acc > 0.f) ? acc : 0.1f * acc;
    }
    __syncwarp();

    // cls layer 3: 30 -> 2
    if (lane < 2) {
        float acc = __ldg(&b3[lane]);
        for (int k = 0; k < 30; k++) acc += B[k] * __ldg(&W3[k * 2 + lane]);
        out[node * 2 + lane] = acc;
    }
}

// ---------------- launch ----------------------------------------------------
extern "C" void kernel_launch(void* const* d_in, const int* in_sizes, int n_in,
                              void* d_out, int out_size) {
    const float* x = (const float*)d_in[0];
    const int* ei[3] = { (const int*)d_in[1], (const int*)d_in[2], (const int*)d_in[3] };
    // per-tag params: Wl, bl, Wr, br, att, bo at indices 4 + 6*t ...
    const float* proj_W = (const float*)d_in[22];
    const float* proj_b = (const float*)d_in[23];
    const float* W1 = (const float*)d_in[24];
    const float* b1 = (const float*)d_in[25];
    const float* W2 = (const float*)d_in[26];
    const float* b2 = (const float*)d_in[27];
    const float* W3 = (const float*)d_in[28];
    const float* b3 = (const float*)d_in[29];
    float* out = (float*)d_out;

    for (int t = 0; t < 3; ++t) {
        const float* Wl = (const float*)d_in[4 + 6 * t + 0];
        const float* bl = (const float*)d_in[4 + 6 * t + 1];
        const float* Wr = (const float*)d_in[4 + 6 * t + 2];
        const float* br = (const float*)d_in[4 + 6 * t + 3];
        const float* att = (const float*)d_in[4 + 6 * t + 4];
        const float* bo = (const float*)d_in[4 + 6 * t + 5];
        const int* src = ei[t];          // row 0
        const int* dst = ei[t] + EE;     // row 1

        zero_cursor_kernel<<<(NN + 255) / 256, 256>>>();
        hist_kernel<<<2048, 256>>>(dst);
        scan1_kernel<<<SCAN_NB, SCAN_BS>>>();
        scan2_kernel<<<1, SCAN_BS>>>();
        scan3_kernel<<<SCAN_NB, SCAN_BS>>>();
        scatter_kernel<<<2048, 256>>>(src, dst);
        lin_kernel<<<(NN * 50 + 255) / 256, 256>>>(x, Wl, bl, Wr, br);
        aggregate_kernel<<<(NN * 32 + 255) / 256, 256>>>(att, bo, t * 50);
    }

    mlp_kernel<<<(NN + 7) / 8, 256>>>(proj_W, proj_b, W1, b1, W2, b2, W3, b3, out);
}

// round 6
// speedup vs baseline: 1.4301x; 1.4301x over previous
#include <cuda_runtime.h>
#include <math.h>

#define NN 100000
#define EE 1600000
#define SCAN_BS 1024
#define SCAN_NB ((NN + SCAN_BS - 1) / SCAN_BS)   // 98

// ---------------- scratch (static device globals; no allocation) ------------
__device__ float g_xl[NN * 50];
__device__ float g_xr[NN * 50];
__device__ float g_h[NN * 150];
__device__ float g_p[(size_t)NN * 160];
__device__ float g_q[(size_t)NN * 80];
__device__ int   g_rowptr[NN + 1];
__device__ int   g_cursor[NN];
__device__ int   g_csr[EE];
__device__ int   g_bsums[SCAN_BS];

// Resolve scratch buffers INSIDE device code (passing __device__ symbols as
// kernel arguments from host code yields the host shadow symbol — round-3/4 bug).
__device__ __forceinline__ float* sel_buf(int s) {
    return (s == 0) ? g_h : ((s == 1) ? g_p : g_q);
}

// ---------------- CSR build (verbatim round-2, known good) ------------------
__global__ void zero_cursor_kernel() {
    int i = blockIdx.x * blockDim.x + threadIdx.x;
    if (i < NN) g_cursor[i] = 0;
}

__global__ void hist_kernel(const int* __restrict__ dst) {
    for (int e = blockIdx.x * blockDim.x + threadIdx.x; e < EE;
         e += gridDim.x * blockDim.x) {
        atomicAdd(&g_cursor[dst[e]], 1);
    }
}

__global__ void scan1_kernel() {
    __shared__ int sh[SCAN_BS];
    int tid = threadIdx.x;
    int i = blockIdx.x * SCAN_BS + tid;
    int v = (i < NN) ? g_cursor[i] : 0;
    sh[tid] = v;
    __syncthreads();
    for (int off = 1; off < SCAN_BS; off <<= 1) {
        int t = (tid >= off) ? sh[tid - off] : 0;
        __syncthreads();
        sh[tid] += t;
        __syncthreads();
    }
    if (i < NN) g_rowptr[i] = sh[tid] - v;
    if (tid == SCAN_BS - 1) g_bsums[blockIdx.x] = sh[tid];
}

__global__ void scan2_kernel() {
    __shared__ int sh[SCAN_BS];
    int tid = threadIdx.x;
    int v = (tid < SCAN_NB) ? g_bsums[tid] : 0;
    sh[tid] = v;
    __syncthreads();
    for (int off = 1; off < SCAN_BS; off <<= 1) {
        int t = (tid >= off) ? sh[tid - off] : 0;
        __syncthreads();
        sh[tid] += t;
        __syncthreads();
    }
    if (tid < SCAN_NB) g_bsums[tid] = sh[tid] - v;
}

__global__ void scan3_kernel() {
    int i = blockIdx.x * SCAN_BS + threadIdx.x;
    if (i < NN) {
        int r = g_rowptr[i] + g_bsums[blockIdx.x];
        g_rowptr[i] = r;
        g_cursor[i] = r;
    }
    if (blockIdx.x == 0 && threadIdx.x == 0) g_rowptr[NN] = EE;
}

__global__ void scatter_kernel(const int* __restrict__ src,
                               const int* __restrict__ dst) {
    for (int e = blockIdx.x * blockDim.x + threadIdx.x; e < EE;
         e += gridDim.x * blockDim.x) {
        int p = atomicAdd(&g_cursor[dst[e]], 1);
        g_csr[p] = src[e];
    }
}

// ---------------- linear transforms (verbatim round-2) ----------------------
__global__ void lin_kernel(const float* __restrict__ x,
                           const float* __restrict__ Wl, const float* __restrict__ bl,
                           const float* __restrict__ Wr, const float* __restrict__ br) {
    int id = blockIdx.x * blockDim.x + threadIdx.x;
    if (id >= NN * 50) return;
    int node = id / 50;
    int c = id - node * 50;
    const float* xrow = x + node * 25;
    float al = bl[c], ar = br[c];
#pragma unroll
    for (int k = 0; k < 25; k++) {
        float xv = __ldg(&xrow[k]);
        al += xv * __ldg(&Wl[k * 50 + c]);
        ar += xv * __ldg(&Wr[k * 50 + c]);
    }
    g_xl[id] = al;
    g_xr[id] = ar;
}

// ---------------- GATv2 aggregate (round-2, expf -> __expf) ------------------
__global__ void aggregate_kernel(const float* __restrict__ att,
                                 const float* __restrict__ bo,
                                 int tag_off) {
    int warp = (blockIdx.x * blockDim.x + threadIdx.x) >> 5;
    int lane = threadIdx.x & 31;
    if (warp >= NN) return;
    const int i = warp;
    bool hi = (lane < 18);

    float xr0 = g_xr[i * 50 + lane];
    float xr1 = hi ? g_xr[i * 50 + 32 + lane] : 0.f;
    float xl0 = g_xl[i * 50 + lane];
    float xl1 = hi ? g_xl[i * 50 + 32 + lane] : 0.f;
    float a0 = __ldg(&att[lane]);
    float a1 = hi ? __ldg(&att[32 + lane]) : 0.f;

    // self loop
    float m0 = xl0 + xr0; m0 = (m0 > 0.f) ? m0 : 0.2f * m0;
    float m1 = xl1 + xr1; m1 = (m1 > 0.f) ? m1 : 0.2f * m1;
    float p = m0 * a0 + m1 * a1;
#pragma unroll
    for (int o = 16; o; o >>= 1) p += __shfl_xor_sync(0xFFFFFFFFu, p, o);
    float w = __expf(p);
    float denom = w;
    float acc0 = w * xl0;
    float acc1 = w * xl1;

    int beg = g_rowptr[i];
    int end = g_rowptr[i + 1];
    for (int e = beg; e < end; ++e) {
        int j = g_csr[e];
        float y0 = g_xl[j * 50 + lane];
        float y1 = hi ? g_xl[j * 50 + 32 + lane] : 0.f;
        float q0 = y0 + xr0; q0 = (q0 > 0.f) ? q0 : 0.2f * q0;
        float q1 = y1 + xr1; q1 = (q1 > 0.f) ? q1 : 0.2f * q1;
        float s = q0 * a0 + q1 * a1;
#pragma unroll
        for (int o = 16; o; o >>= 1) s += __shfl_xor_sync(0xFFFFFFFFu, s, o);
        float we = __expf(s);
        denom += we;
        acc0 += we * y0;
        acc1 += we * y1;
    }

    float inv = 1.f / denom;
    float o0 = acc0 * inv + __ldg(&bo[lane]);
    o0 = (o0 > 0.f) ? o0 : 0.1f * o0;
    g_h[i * 150 + tag_off + lane] = o0;
    if (hi) {
        float o1 = acc1 * inv + __ldg(&bo[32 + lane]);
        o1 = (o1 > 0.f) ? o1 : 0.1f * o1;
        g_h[i * 150 + tag_off + 32 + lane] = o1;
    }
}

// ---------------- register-tiled GEMM (plain scalar FMA) ---------------------
// 256 threads, 64-node tile. tx in [0,TXN), ty in [0,256/TXN), MPT nodes/thread
// (MPT*256/TXN == 64), NT (even) output cols/thread, NPAD = TXN*NT >= NOUT.
// in/out scratch buffers selected by index INSIDE device code.
template<int TXN, int MPT, int NT, int KDIM, int KT, int NOUT, int INSTR, int OUTSTR, bool LEAKY>
__global__ __launch_bounds__(256) void gemm_kernel(int in_sel, int out_sel,
                                                   const float* __restrict__ W,
                                                   const float* __restrict__ b) {
    const float* in = sel_buf(in_sel);
    float* out = sel_buf(out_sel);
    constexpr int NPAD = TXN * NT;
    __shared__ __align__(16) float shW[KT][NPAD];
    __shared__ float shH[64][KT + 1];
    int tid = threadIdx.x;
    int tx = tid % TXN, ty = tid / TXN;
    int node0 = blockIdx.x * 64;

    float acc[MPT][NT];
#pragma unroll
    for (int mm = 0; mm < MPT; mm++)
#pragma unroll
        for (int j = 0; j < NT; j++) acc[mm][j] = 0.f;

    for (int kt = 0; kt < KDIM; kt += KT) {
        for (int idx = tid; idx < KT * NPAD; idx += 256) {
            int k = idx / NPAD, c = idx - k * NPAD;
            shW[k][c] = (c < NOUT) ? __ldg(&W[(size_t)(kt + k) * NOUT + c]) : 0.f;
        }
        for (int idx = tid; idx < 64 * KT; idx += 256) {
            int m = idx / KT, k = idx - m * KT;
            int n = node0 + m;
            shH[m][k] = (n < NN) ? in[(size_t)n * INSTR + kt + k] : 0.f;
        }
        __syncthreads();
#pragma unroll 2
        for (int kk = 0; kk < KT; ++kk) {
            float h[MPT];
#pragma unroll
            for (int mm = 0; mm < MPT; mm++) h[mm] = shH[ty * MPT + mm][kk];
#pragma unroll
            for (int j = 0; j < NT / 2; j++) {
                float2 w2 = *reinterpret_cast<const float2*>(&shW[kk][tx * NT + 2 * j]);
#pragma unroll
                for (int mm = 0; mm < MPT; mm++) {
                    acc[mm][2 * j]     += w2.x * h[mm];
                    acc[mm][2 * j + 1] += w2.y * h[mm];
                }
            }
        }
        __syncthreads();
    }

#pragma unroll
    for (int mm = 0; mm < MPT; mm++) {
        int n = node0 + ty * MPT + mm;
        if (n >= NN) continue;
#pragma unroll
        for (int j = 0; j < NT; j++) {
            int c = tx * NT + j;
            if (c < NOUT) {
                float r = acc[mm][j] + __ldg(&b[c]);
                if (LEAKY) r = (r > 0.f) ? r : 0.1f * r;
                out[(size_t)n * OUTSTR + c] = r;
            }
        }
    }
}

// ---------------- cls2 (75->30 leaky) + cls3 (30->2) fused -------------------
__global__ __launch_bounds__(256) void cls23_kernel(const float* __restrict__ W2,
                                                    const float* __restrict__ b2,
                                                    const float* __restrict__ W3,
                                                    const float* __restrict__ b3,
                                                    float* __restrict__ out) {
    __shared__ float shH[64][76];
    __shared__ __align__(16) float shW[75][32];
    __shared__ float sh2[64][32];
    int tid = threadIdx.x;
    int node0 = blockIdx.x * 64;

    for (int idx = tid; idx < 75 * 32; idx += 256) {
        int k = idx >> 5, c = idx & 31;
        shW[k][c] = (c < 30) ? __ldg(&W2[k * 30 + c]) : 0.f;
    }
    for (int idx = tid; idx < 64 * 75; idx += 256) {
        int m = idx / 75, k = idx - m * 75;
        int n = node0 + m;
        shH[m][k] = (n < NN) ? g_q[(size_t)n * 80 + k] : 0.f;
    }
    __syncthreads();

    {
        int tx = tid & 15, ty = tid >> 4;       // tx: 16 col-pairs, ty: 16 row groups
        float acc[4][2];
#pragma unroll
        for (int mm = 0; mm < 4; mm++) { acc[mm][0] = 0.f; acc[mm][1] = 0.f; }
#pragma unroll 3
        for (int k = 0; k < 75; k++) {
            float2 w2 = *reinterpret_cast<const float2*>(&shW[k][tx * 2]);
#pragma unroll
            for (int mm = 0; mm < 4; mm++) {
                float h = shH[ty * 4 + mm][k];
                acc[mm][0] += w2.x * h;
                acc[mm][1] += w2.y * h;
            }
        }
        int c = tx * 2;
        if (c < 30) {
            float bb0 = __ldg(&b2[c]), bb1 = __ldg(&b2[c + 1]);
#pragma unroll
            for (int mm = 0; mm < 4; mm++) {
                float r0 = acc[mm][0] + bb0; r0 = (r0 > 0.f) ? r0 : 0.1f * r0;
                float r1 = acc[mm][1] + bb1; r1 = (r1 > 0.f) ? r1 : 0.1f * r1;
                sh2[ty * 4 + mm][c] = r0;
                sh2[ty * 4 + mm][c + 1] = r1;
            }
        }
    }
    __syncthreads();

    if (tid < 128) {
        int m = tid >> 1, col = tid & 1;
        int n = node0 + m;
        if (n < NN) {
            float acc = __ldg(&b3[col]);
#pragma unroll
            for (int k = 0; k < 30; k++) acc += sh2[m][k] * __ldg(&W3[k * 2 + col]);
            out[(size_t)n * 2 + col] = acc;
        }
    }
}

// ---------------- launch ----------------------------------------------------
extern "C" void kernel_launch(void* const* d_in, const int* in_sizes, int n_in,
                              void* d_out, int out_size) {
    const float* x = (const float*)d_in[0];
    const int* ei[3] = { (const int*)d_in[1], (const int*)d_in[2], (const int*)d_in[3] };
    const float* proj_W = (const float*)d_in[22];
    const float* proj_b = (const float*)d_in[23];
    const float* W1 = (const float*)d_in[24];
    const float* b1 = (const float*)d_in[25];
    const float* W2 = (const float*)d_in[26];
    const float* b2 = (const float*)d_in[27];
    const float* W3 = (const float*)d_in[28];
    const float* b3 = (const float*)d_in[29];
    float* out = (float*)d_out;

    for (int t = 0; t < 3; ++t) {
        const float* Wl = (const float*)d_in[4 + 6 * t + 0];
        const float* bl = (const float*)d_in[4 + 6 * t + 1];
        const float* Wr = (const float*)d_in[4 + 6 * t + 2];
        const float* br = (const float*)d_in[4 + 6 * t + 3];
        const float* att = (const float*)d_in[4 + 6 * t + 4];
        const float* bo = (const float*)d_in[4 + 6 * t + 5];
        const int* src = ei[t];          // row 0
        const int* dst = ei[t] + EE;     // row 1

        zero_cursor_kernel<<<(NN + 255) / 256, 256>>>();
        hist_kernel<<<2048, 256>>>(dst);
        scan1_kernel<<<SCAN_NB, SCAN_BS>>>();
        scan2_kernel<<<1, SCAN_BS>>>();
        scan3_kernel<<<SCAN_NB, SCAN_BS>>>();
        scatter_kernel<<<2048, 256>>>(src, dst);
        lin_kernel<<<(NN * 50 + 255) / 256, 256>>>(x, Wl, bl, Wr, br);
        aggregate_kernel<<<(NN * 32 + 255) / 256, 256>>>(att, bo, t * 50);
    }

    // proj: 150 -> 150 (no act), g_h (sel 0, stride 150) -> g_p (sel 1, stride 160)
    gemm_kernel<16, 4, 10, 150, 50, 150, 150, 160, false>
        <<<(NN + 63) / 64, 256>>>(0, 1, proj_W, proj_b);
    // cls1: 150 -> 75 (leaky 0.1), g_p (sel 1, stride 160) -> g_q (sel 2, stride 80)
    gemm_kernel<8, 2, 10, 150, 50, 75, 160, 80, true>
        <<<(NN + 63) / 64, 256>>>(1, 2, W1, b1);
    // cls2 + cls3 fused
    cls23_kernel<<<(NN + 63) / 64, 256>>>(W2, b2, W3, b3, out);
}

// round 7
// speedup vs baseline: 1.5460x; 1.0810x over previous
#include <cuda_runtime.h>
#include <math.h>

#define NN 100000
#define EE 1600000
#define NN3 (3 * NN)
#define EE3 (3 * EE)
#define SCAN_BS 1024
#define SCAN_NB ((NN3 + SCAN_BS - 1) / SCAN_BS)   // 293

// ---------------- scratch (static device globals; no allocation) ------------
__device__ float g_xl[(size_t)3 * NN * 64];   // padded rows: stride 64
__device__ float g_xr[(size_t)3 * NN * 64];
__device__ float g_h[(size_t)NN * 150];
__device__ float g_p[(size_t)NN * 160];
__device__ float g_q[(size_t)NN * 80];
__device__ int   g_rowptr[NN3 + 1];
__device__ int   g_cursor[NN3];
__device__ int   g_csr[EE3];
__device__ int   g_bsums[SCAN_BS];

// Resolve scratch buffers INSIDE device code (host-side __device__ symbol
// arguments are the round-3/4 bug — never pass g_* from kernel_launch).
__device__ __forceinline__ float* sel_buf(int s) {
    return (s == 0) ? g_h : ((s == 1) ? g_p : g_q);
}

// ---------------- CSR build (fused over 3 relations) ------------------------
__global__ void zero_cursor_kernel() {
    int i = blockIdx.x * blockDim.x + threadIdx.x;
    if (i < NN3) g_cursor[i] = 0;
}

__global__ void hist_kernel(const int* __restrict__ d0, const int* __restrict__ d1,
                            const int* __restrict__ d2) {
    for (int e = blockIdx.x * blockDim.x + threadIdx.x; e < EE;
         e += gridDim.x * blockDim.x) {
        atomicAdd(&g_cursor[__ldg(&d0[e])], 1);
        atomicAdd(&g_cursor[NN + __ldg(&d1[e])], 1);
        atomicAdd(&g_cursor[2 * NN + __ldg(&d2[e])], 1);
    }
}

__global__ void scan1_kernel() {
    __shared__ int sh[SCAN_BS];
    int tid = threadIdx.x;
    int i = blockIdx.x * SCAN_BS + tid;
    int v = (i < NN3) ? g_cursor[i] : 0;
    sh[tid] = v;
    __syncthreads();
    for (int off = 1; off < SCAN_BS; off <<= 1) {
        int t = (tid >= off) ? sh[tid - off] : 0;
        __syncthreads();
        sh[tid] += t;
        __syncthreads();
    }
    if (i < NN3) g_rowptr[i] = sh[tid] - v;
    if (tid == SCAN_BS - 1) g_bsums[blockIdx.x] = sh[tid];
}

__global__ void scan2_kernel() {
    __shared__ int sh[SCAN_BS];
    int tid = threadIdx.x;
    int v = (tid < SCAN_NB) ? g_bsums[tid] : 0;
    sh[tid] = v;
    __syncthreads();
    for (int off = 1; off < SCAN_BS; off <<= 1) {
        int t = (tid >= off) ? sh[tid - off] : 0;
        __syncthreads();
        sh[tid] += t;
        __syncthreads();
    }
    if (tid < SCAN_NB) g_bsums[tid] = sh[tid] - v;
}

__global__ void scan3_kernel() {
    int i = blockIdx.x * SCAN_BS + threadIdx.x;
    if (i < NN3) {
        int r = g_rowptr[i] + g_bsums[blockIdx.x];
        g_rowptr[i] = r;
        g_cursor[i] = r;
    }
    if (blockIdx.x == 0 && threadIdx.x == 0) g_rowptr[NN3] = EE3;
}

__global__ void scatter_kernel(const int* __restrict__ s0, const int* __restrict__ d0,
                               const int* __restrict__ s1, const int* __restrict__ d1,
                               const int* __restrict__ s2, const int* __restrict__ d2) {
    for (int e = blockIdx.x * blockDim.x + threadIdx.x; e < EE;
         e += gridDim.x * blockDim.x) {
        int p0 = atomicAdd(&g_cursor[__ldg(&d0[e])], 1);
        g_csr[p0] = __ldg(&s0[e]);
        int p1 = atomicAdd(&g_cursor[NN + __ldg(&d1[e])], 1);
        g_csr[p1] = __ldg(&s1[e]);
        int p2 = atomicAdd(&g_cursor[2 * NN + __ldg(&d2[e])], 1);
        g_csr[p2] = __ldg(&s2[e]);
    }
}

// ---------------- fused linear transforms for all 3 relations ---------------
struct LinParams {
    const float* Wl[3]; const float* bl[3];
    const float* Wr[3]; const float* br[3];
};

__global__ __launch_bounds__(256) void lin_kernel(const float* __restrict__ x, LinParams P) {
    __shared__ __align__(16) float sW[6][25 * 50];   // l0..l2, r0..r2
    __shared__ float sB[6][64];
    __shared__ float sX[32][26];
    int tid = threadIdx.x;

    for (int i = tid; i < 25 * 50; i += 256) {
#pragma unroll
        for (int t = 0; t < 3; t++) {
            sW[t][i]     = __ldg(&P.Wl[t][i]);
            sW[3 + t][i] = __ldg(&P.Wr[t][i]);
        }
    }
    if (tid < 50) {
#pragma unroll
        for (int t = 0; t < 3; t++) {
            sB[t][tid]     = __ldg(&P.bl[t][tid]);
            sB[3 + t][tid] = __ldg(&P.br[t][tid]);
        }
    }
    int node0 = blockIdx.x * 32;
    for (int i = tid; i < 32 * 25; i += 256) {
        int nl = i / 25, k = i - nl * 25;
        int n = node0 + nl;
        sX[nl][k] = (n < NN) ? __ldg(&x[(size_t)n * 25 + k]) : 0.f;
    }
    __syncthreads();

#pragma unroll
    for (int s = 0; s < 8; ++s) {
        int slot = s * 256 + tid;           // 0..2047 = 32 nodes x 64 cols
        int nl = slot >> 6, c = slot & 63;
        if (c >= 50) continue;
        int n = node0 + nl;
        if (n >= NN) continue;
        float al0 = sB[0][c], al1 = sB[1][c], al2 = sB[2][c];
        float ar0 = sB[3][c], ar1 = sB[4][c], ar2 = sB[5][c];
#pragma unroll
        for (int k = 0; k < 25; k++) {
            float xv = sX[nl][k];
            al0 += xv * sW[0][k * 50 + c];
            al1 += xv * sW[1][k * 50 + c];
            al2 += xv * sW[2][k * 50 + c];
            ar0 += xv * sW[3][k * 50 + c];
            ar1 += xv * sW[4][k * 50 + c];
            ar2 += xv * sW[5][k * 50 + c];
        }
        size_t o = (size_t)n * 64 + c;
        const size_t R = (size_t)NN * 64;
        g_xl[o] = al0;         g_xr[o] = ar0;
        g_xl[R + o] = al1;     g_xr[R + o] = ar1;
        g_xl[2 * R + o] = al2; g_xr[2 * R + o] = ar2;
    }
}

// ---------------- GATv2 aggregate: one warp per (relation, node) -------------
struct AttParams { const float* att[3]; const float* bo[3]; };

__global__ __launch_bounds__(256) void aggregate_kernel(AttParams P) {
    int warp = (blockIdx.x * blockDim.x + threadIdx.x) >> 5;
    if (warp >= NN3) return;
    int lane = threadIdx.x & 31;
    int t = warp / NN;
    int i = warp - t * NN;
    bool hi = (lane < 18);

    const float* xlb = g_xl + (size_t)t * NN * 64;
    const float* xrb = g_xr + (size_t)t * NN * 64;

    float xr0 = xrb[(size_t)i * 64 + lane];
    float xr1 = hi ? xrb[(size_t)i * 64 + 32 + lane] : 0.f;
    float xl0 = xlb[(size_t)i * 64 + lane];
    float xl1 = hi ? xlb[(size_t)i * 64 + 32 + lane] : 0.f;
    float a0 = __ldg(&P.att[t][lane]);
    float a1 = hi ? __ldg(&P.att[t][32 + lane]) : 0.f;

    // self loop
    float m0 = xl0 + xr0; m0 = (m0 > 0.f) ? m0 : 0.2f * m0;
    float m1 = xl1 + xr1; m1 = (m1 > 0.f) ? m1 : 0.2f * m1;
    float p = m0 * a0 + m1 * a1;
#pragma unroll
    for (int o = 16; o; o >>= 1) p += __shfl_xor_sync(0xFFFFFFFFu, p, o);
    float w = __expf(p);
    float denom = w;
    float acc0 = w * xl0;
    float acc1 = w * xl1;

    int beg = g_rowptr[t * NN + i];
    int end = g_rowptr[t * NN + i + 1];
    int e = beg;
    for (; e + 4 <= end; e += 4) {
        int j0 = g_csr[e], j1 = g_csr[e + 1], j2 = g_csr[e + 2], j3 = g_csr[e + 3];
        const float* r0 = xlb + (size_t)j0 * 64;
        const float* r1 = xlb + (size_t)j1 * 64;
        const float* r2 = xlb + (size_t)j2 * 64;
        const float* r3 = xlb + (size_t)j3 * 64;
        float y00 = r0[lane], y01 = hi ? r0[32 + lane] : 0.f;
        float y10 = r1[lane], y11 = hi ? r1[32 + lane] : 0.f;
        float y20 = r2[lane], y21 = hi ? r2[32 + lane] : 0.f;
        float y30 = r3[lane], y31 = hi ? r3[32 + lane] : 0.f;

        float q;
        q = y00 + xr0; q = (q > 0.f) ? q : 0.2f * q; float s0 = q * a0;
        q = y01 + xr1; q = (q > 0.f) ? q : 0.2f * q; s0 += q * a1;
        q = y10 + xr0; q = (q > 0.f) ? q : 0.2f * q; float s1 = q * a0;
        q = y11 + xr1; q = (q > 0.f) ? q : 0.2f * q; s1 += q * a1;
        q = y20 + xr0; q = (q > 0.f) ? q : 0.2f * q; float s2 = q * a0;
        q = y21 + xr1; q = (q > 0.f) ? q : 0.2f * q; s2 += q * a1;
        q = y30 + xr0; q = (q > 0.f) ? q : 0.2f * q; float s3 = q * a0;
        q = y31 + xr1; q = (q > 0.f) ? q : 0.2f * q; s3 += q * a1;
#pragma unroll
        for (int o = 16; o; o >>= 1) {
            s0 += __shfl_xor_sync(0xFFFFFFFFu, s0, o);
            s1 += __shfl_xor_sync(0xFFFFFFFFu, s1, o);
            s2 += __shfl_xor_sync(0xFFFFFFFFu, s2, o);
            s3 += __shfl_xor_sync(0xFFFFFFFFu, s3, o);
        }
        float w0 = __expf(s0), w1 = __expf(s1), w2 = __expf(s2), w3 = __expf(s3);
        denom += (w0 + w1) + (w2 + w3);
        acc0 += w0 * y00; acc1 += w0 * y01;
        acc0 += w1 * y10; acc1 += w1 * y11;
        acc0 += w2 * y20; acc1 += w2 * y21;
        acc0 += w3 * y30; acc1 += w3 * y31;
    }
    for (; e < end; ++e) {
        int j = g_csr[e];
        const float* r = xlb + (size_t)j * 64;
        float y0 = r[lane];
        float y1 = hi ? r[32 + lane] : 0.f;
        float q0 = y0 + xr0; q0 = (q0 > 0.f) ? q0 : 0.2f * q0;
        float q1 = y1 + xr1; q1 = (q1 > 0.f) ? q1 : 0.2f * q1;
        float s = q0 * a0 + q1 * a1;
#pragma unroll
        for (int o = 16; o; o >>= 1) s += __shfl_xor_sync(0xFFFFFFFFu, s, o);
        float we = __expf(s);
        denom += we;
        acc0 += we * y0;
        acc1 += we * y1;
    }

    float inv = 1.f / denom;
    float o0 = acc0 * inv + __ldg(&P.bo[t][lane]);
    o0 = (o0 > 0.f) ? o0 : 0.1f * o0;
    g_h[(size_t)i * 150 + t * 50 + lane] = o0;
    if (hi) {
        float o1 = acc1 * inv + __ldg(&P.bo[t][32 + lane]);
        o1 = (o1 > 0.f) ? o1 : 0.1f * o1;
        g_h[(size_t)i * 150 + t * 50 + 32 + lane] = o1;
    }
}

// ---------------- register-tiled GEMM (plain scalar FMA, round-6 verbatim) --
template<int TXN, int MPT, int NT, int KDIM, int KT, int NOUT, int INSTR, int OUTSTR, bool LEAKY>
__global__ __launch_bounds__(256) void gemm_kernel(int in_sel, int out_sel,
                                                   const float* __restrict__ W,
                                                   const float* __restrict__ b) {
    const float* in = sel_buf(in_sel);
    float* out = sel_buf(out_sel);
    constexpr int NPAD = TXN * NT;
    __shared__ __align__(16) float shW[KT][NPAD];
    __shared__ float shH[64][KT + 1];
    int tid = threadIdx.x;
    int tx = tid % TXN, ty = tid / TXN;
    int node0 = blockIdx.x * 64;

    float acc[MPT][NT];
#pragma unroll
    for (int mm = 0; mm < MPT; mm++)
#pragma unroll
        for (int j = 0; j < NT; j++) acc[mm][j] = 0.f;

    for (int kt = 0; kt < KDIM; kt += KT) {
        for (int idx = tid; idx < KT * NPAD; idx += 256) {
            int k = idx / NPAD, c = idx - k * NPAD;
            shW[k][c] = (c < NOUT) ? __ldg(&W[(size_t)(kt + k) * NOUT + c]) : 0.f;
        }
        for (int idx = tid; idx < 64 * KT; idx += 256) {
            int m = idx / KT, k = idx - m * KT;
            int n = node0 + m;
            shH[m][k] = (n < NN) ? in[(size_t)n * INSTR + kt + k] : 0.f;
        }
        __syncthreads();
#pragma unroll 2
        for (int kk = 0; kk < KT; ++kk) {
            float h[MPT];
#pragma unroll
            for (int mm = 0; mm < MPT; mm++) h[mm] = shH[ty * MPT + mm][kk];
#pragma unroll
            for (int j = 0; j < NT / 2; j++) {
                float2 w2 = *reinterpret_cast<const float2*>(&shW[kk][tx * NT + 2 * j]);
#pragma unroll
                for (int mm = 0; mm < MPT; mm++) {
                    acc[mm][2 * j]     += w2.x * h[mm];
                    acc[mm][2 * j + 1] += w2.y * h[mm];
                }
            }
        }
        __syncthreads();
    }

#pragma unroll
    for (int mm = 0; mm < MPT; mm++) {
        int n = node0 + ty * MPT + mm;
        if (n >= NN) continue;
#pragma unroll
        for (int j = 0; j < NT; j++) {
            int c = tx * NT + j;
            if (c < NOUT) {
                float r = acc[mm][j] + __ldg(&b[c]);
                if (LEAKY) r = (r > 0.f) ? r : 0.1f * r;
                out[(size_t)n * OUTSTR + c] = r;
            }
        }
    }
}

// ---------------- cls2 (75->30 leaky) + cls3 (30->2) fused (round-6 verbatim)
__global__ __launch_bounds__(256) void cls23_kernel(const float* __restrict__ W2,
                                                    const float* __restrict__ b2,
                                                    const float* __restrict__ W3,
                                                    const float* __restrict__ b3,
                                                    float* __restrict__ out) {
    __shared__ float shH[64][76];
    __shared__ __align__(16) float shW[75][32];
    __shared__ float sh2[64][32];
    int tid = threadIdx.x;
    int node0 = blockIdx.x * 64;

    for (int idx = tid; idx < 75 * 32; idx += 256) {
        int k = idx >> 5, c = idx & 31;
        shW[k][c] = (c < 30) ? __ldg(&W2[k * 30 + c]) : 0.f;
    }
    for (int idx = tid; idx < 64 * 75; idx += 256) {
        int m = idx / 75, k = idx - m * 75;
        int n = node0 + m;
        shH[m][k] = (n < NN) ? g_q[(size_t)n * 80 + k] : 0.f;
    }
    __syncthreads();

    {
        int tx = tid & 15, ty = tid >> 4;
        float acc[4][2];
#pragma unroll
        for (int mm = 0; mm < 4; mm++) { acc[mm][0] = 0.f; acc[mm][1] = 0.f; }
#pragma unroll 3
        for (int k = 0; k < 75; k++) {
            float2 w2 = *reinterpret_cast<const float2*>(&shW[k][tx * 2]);
#pragma unroll
            for (int mm = 0; mm < 4; mm++) {
                float h = shH[ty * 4 + mm][k];
                acc[mm][0] += w2.x * h;
                acc[mm][1] += w2.y * h;
            }
        }
        int c = tx * 2;
        if (c < 30) {
            float bb0 = __ldg(&b2[c]), bb1 = __ldg(&b2[c + 1]);
#pragma unroll
            for (int mm = 0; mm < 4; mm++) {
                float r0 = acc[mm][0] + bb0; r0 = (r0 > 0.f) ? r0 : 0.1f * r0;
                float r1 = acc[mm][1] + bb1; r1 = (r1 > 0.f) ? r1 : 0.1f * r1;
                sh2[ty * 4 + mm][c] = r0;
                sh2[ty * 4 + mm][c + 1] = r1;
            }
        }
    }
    __syncthreads();

    if (tid < 128) {
        int m = tid >> 1, col = tid & 1;
        int n = node0 + m;
        if (n < NN) {
            float acc = __ldg(&b3[col]);
#pragma unroll
            for (int k = 0; k < 30; k++) acc += sh2[m][k] * __ldg(&W3[k * 2 + col]);
            out[(size_t)n * 2 + col] = acc;
        }
    }
}

// ---------------- launch ----------------------------------------------------
extern "C" void kernel_launch(void* const* d_in, const int* in_sizes, int n_in,
                              void* d_out, int out_size) {
    const float* x = (const float*)d_in[0];
    const int* ei[3] = { (const int*)d_in[1], (const int*)d_in[2], (const int*)d_in[3] };
    const float* proj_W = (const float*)d_in[22];
    const float* proj_b = (const float*)d_in[23];
    const float* W1 = (const float*)d_in[24];
    const float* b1 = (const float*)d_in[25];
    const float* W2 = (const float*)d_in[26];
    const float* b2 = (const float*)d_in[27];
    const float* W3 = (const float*)d_in[28];
    const float* b3 = (const float*)d_in[29];
    float* out = (float*)d_out;

    LinParams LP;
    AttParams AP;
    for (int t = 0; t < 3; ++t) {
        LP.Wl[t]  = (const float*)d_in[4 + 6 * t + 0];
        LP.bl[t]  = (const float*)d_in[4 + 6 * t + 1];
        LP.Wr[t]  = (const float*)d_in[4 + 6 * t + 2];
        LP.br[t]  = (const float*)d_in[4 + 6 * t + 3];
        AP.att[t] = (const float*)d_in[4 + 6 * t + 4];
        AP.bo[t]  = (const float*)d_in[4 + 6 * t + 5];
    }
    const int* s0 = ei[0], *d0 = ei[0] + EE;
    const int* s1 = ei[1], *d1 = ei[1] + EE;
    const int* s2 = ei[2], *d2 = ei[2] + EE;

    zero_cursor_kernel<<<(NN3 + 255) / 256, 256>>>();
    hist_kernel<<<2048, 256>>>(d0, d1, d2);
    scan1_kernel<<<SCAN_NB, SCAN_BS>>>();
    scan2_kernel<<<1, SCAN_BS>>>();
    scan3_kernel<<<SCAN_NB, SCAN_BS>>>();
    scatter_kernel<<<2048, 256>>>(s0, d0, s1, d1, s2, d2);

    lin_kernel<<<(NN + 31) / 32, 256>>>(x, LP);
    aggregate_kernel<<<(NN3 * 32 + 255) / 256, 256>>>(AP);

    // proj: 150 -> 150 (no act), g_h (sel 0, stride 150) -> g_p (sel 1, stride 160)
    gemm_kernel<16, 4, 10, 150, 50, 150, 150, 160, false>
        <<<(NN + 63) / 64, 256>>>(0, 1, proj_W, proj_b);
    // cls1: 150 -> 75 (leaky 0.1), g_p (sel 1, stride 160) -> g_q (sel 2, stride 80)
    gemm_kernel<8, 2, 10, 150, 50, 75, 160, 80, true>
        <<<(NN + 63) / 64, 256>>>(1, 2, W1, b1);
    // cls2 + cls3 fused
    cls23_kernel<<<(NN + 63) / 64, 256>>>(W2, b2, W3, b3, out);
}